// round 14
// baseline (speedup 1.0000x reference)
#include <cuda_runtime.h>
#include <mma.h>
#include <cstdint>
#include <cstddef>

using namespace nvcuda;

#define Bv   2
#define Sv   2048
#define Hv   2048
#define NHv  16
#define HDv  128
#define BSv  256
#define Mtot (Bv * Sv)
#define LDQ  (3 * Hv)             // fused QKV row stride (6144)
#define ATT_SCALE 0.08838834764831843f  // 1/sqrt(128)

// ---------------- scratch (__device__ globals, allocation-free rule) -------
__device__ float g_qkv[(size_t)Mtot * LDQ];   // [4096][6144]: Q | K | V
__device__ float g_o[(size_t)Mtot * Hv];
__device__ float g_xr[(size_t)Mtot * Hv];
__device__ float g_wqkv[(size_t)3 * Hv * Hv]; // rows 0..2047 Wq, 2048..4095 Wk, 4096..6143 Wv
__device__ float g_wo[(size_t)Hv * Hv];

// ---------------- helpers ---------------------------------------------------
__device__ __forceinline__ float to_tf32(float x) {
    float y;
    asm("cvt.rna.tf32.f32 %0, %1;" : "=f"(y) : "f"(x));
    return y;
}

__device__ __forceinline__ uint32_t smem_u32(const void* p) {
    uint32_t a;
    asm("{ .reg .u64 t; cvta.to.shared.u64 t, %1; cvt.u32.u64 %0, t; }" : "=r"(a) : "l"(p));
    return a;
}

__device__ __forceinline__ void cp_async16(uint32_t saddr, const void* gptr) {
    asm volatile("cp.async.cg.shared.global [%0], [%1], 16;" :: "r"(saddr), "l"(gptr));
}
#define CP_COMMIT() asm volatile("cp.async.commit_group;")
#define CP_WAIT(n)  asm volatile("cp.async.wait_group %0;" :: "n"(n))
#define CP_WAIT_DYN(cond_one) do { if (cond_one) CP_WAIT(1); else CP_WAIT(0); } while (0)

// ---------------- rounding pre-pass ----------------------------------------
__global__ void __launch_bounds__(256) round_tf32_k(
    const float4* __restrict__ s, float4* __restrict__ d, int n4)
{
    int i = blockIdx.x * 256 + threadIdx.x;
    if (i < n4) {
        float4 v = s[i];
        v.x = to_tf32(v.x); v.y = to_tf32(v.y);
        v.z = to_tf32(v.z); v.w = to_tf32(v.w);
        d[i] = v;
    }
}

// ===========================================================================
// Pipelined tf32 wmma GEMM — R4 configuration (untouched, best measured):
// CTA tile 256x128x32, 8 warps (4x2) with 64x64 warp tiles, 4-stage cp.async.
// ===========================================================================
#define BM 256
#define BN 128
#define BK 32
#define STR 36
#define NSTG 4
#define A_FLTS (BM * STR)
#define B_FLTS (BN * STR)
#define STAGE_FLTS (A_FLTS + B_FLTS)
#define GEMM_SMEM (NSTG * STAGE_FLTS * 4)   // 221184 B -> 1 CTA/SM

__device__ __forceinline__ void stage_load(
    float* stg, const float* __restrict__ Ag, const float* __restrict__ Bg,
    int K, int tid)
{
#pragma unroll
    for (int i = 0; i < 8; i++) {
        int id = tid + i * 256;
        int r = id >> 3, c = id & 7;
        cp_async16(smem_u32(stg + r * STR + c * 4), Ag + (size_t)r * K + c * 4);
    }
#pragma unroll
    for (int i = 0; i < 4; i++) {
        int id = tid + i * 256;
        int r = id >> 3, c = id & 7;
        cp_async16(smem_u32(stg + A_FLTS + r * STR + c * 4), Bg + (size_t)r * K + c * 4);
    }
}

__global__ void __launch_bounds__(256, 1) gemm_pipe(
    const float* __restrict__ A, const float* __restrict__ Bw,
    float* __restrict__ C, int M, int N, int K, int do_round)
{
    extern __shared__ __align__(16) float sm[];

    const int tid = threadIdx.x;
    const int wid = tid >> 5;
    const int m0 = blockIdx.y * BM;
    const int n0 = blockIdx.x * BN;
    const int wm = wid & 3;
    const int wn = wid >> 2;

    const float* Abase = A + (size_t)m0 * K;
    const float* Bbase = Bw + (size_t)n0 * K;
    const int KT = K / BK;

    wmma::fragment<wmma::accumulator, 16, 16, 8, float> acc[4][4];
#pragma unroll
    for (int i = 0; i < 4; i++)
#pragma unroll
        for (int j = 0; j < 4; j++) wmma::fill_fragment(acc[i][j], 0.0f);

#pragma unroll
    for (int t = 0; t < NSTG - 1; t++) {
        stage_load(sm + t * STAGE_FLTS, Abase + t * BK, Bbase + t * BK, K, tid);
        CP_COMMIT();
    }

    for (int kt = 0; kt < KT; kt++) {
        CP_WAIT(NSTG - 2);
        __syncthreads();

        int tn = kt + NSTG - 1;
        if (tn < KT)
            stage_load(sm + (tn % NSTG) * STAGE_FLTS, Abase + (size_t)tn * BK,
                       Bbase + (size_t)tn * BK, K, tid);
        CP_COMMIT();

        const float* sA = sm + (kt % NSTG) * STAGE_FLTS;
        const float* sB = sA + A_FLTS;

#pragma unroll
        for (int kk = 0; kk < 4; kk++) {
            wmma::fragment<wmma::matrix_a, 16, 16, 8, wmma::precision::tf32, wmma::row_major> af[4];
            wmma::fragment<wmma::matrix_b, 16, 16, 8, wmma::precision::tf32, wmma::col_major> bf[4];
#pragma unroll
            for (int i = 0; i < 4; i++)
                wmma::load_matrix_sync(af[i], sA + (wm * 64 + i * 16) * STR + kk * 8, STR);
#pragma unroll
            for (int j = 0; j < 4; j++)
                wmma::load_matrix_sync(bf[j], sB + (wn * 64 + j * 16) * STR + kk * 8, STR);
#pragma unroll
            for (int j = 0; j < 4; j++)
#pragma unroll
                for (int i = 0; i < 4; i++)
                    wmma::mma_sync(acc[i][j], af[i], bf[j], acc[i][j]);
        }
    }

#pragma unroll
    for (int i = 0; i < 4; i++)
#pragma unroll
        for (int j = 0; j < 4; j++) {
            if (do_round) {
#pragma unroll
                for (int t = 0; t < acc[i][j].num_elements; t++)
                    acc[i][j].x[t] = to_tf32(acc[i][j].x[t]);
            }
            wmma::store_matrix_sync(
                C + (size_t)(m0 + wm * 64 + i * 16) * N + n0 + wn * 64 + j * 16,
                acc[i][j], N, wmma::mem_row_major);
        }
}

// ===========================================================================
// Attention, transposed-S formulation (R12, proven best). Q/K/V are read from
// the fused g_qkv buffer with row stride LDQ and column offsets 0/Hv/2*Hv.
// ===========================================================================
#define QT  64
#define AST 132
#define STT 68

#define SM_Q   0
#define SM_KV  (QT * AST)
#define KVSZ   (64 * AST)
#define SM_ST  (SM_KV + 3 * KVSZ)
#define SM_RED (SM_ST + 256 * STT)
#define SM_INV (SM_RED + 256)
#define ATTN_SMEM ((SM_INV + 64) * 4)        // 206080 B

__global__ void __launch_bounds__(256) attn_kernel()
{
    extern __shared__ __align__(16) float sm[];
    float* shQ  = sm + SM_Q;
    float* L0   = sm + SM_KV;
    float* L1   = L0 + KVSZ;
    float* L2   = L1 + KVSZ;
    float* shS  = sm + SM_ST;
    float* shRed = sm + SM_RED;
    float* shInv = sm + SM_INV;

    const int tid = threadIdx.x;
    const int wid = tid >> 5;
    const int qt = gridDim.x - 1 - blockIdx.x;   // expensive tiles first
    const int h  = blockIdx.y;
    const int b  = blockIdx.z;
    const int qbase = qt * QT;
    const int bi = qbase >> 8;

    const float* Qp    = g_qkv + ((size_t)b * Sv + qbase) * LDQ + h * HDv;            // Q block
    const float* Kbase = g_qkv + ((size_t)b * Sv) * LDQ + Hv + h * HDv;               // K block
    const float* Vbase = g_qkv + ((size_t)b * Sv) * LDQ + 2 * Hv + h * HDv;           // V block

    auto load64 = [&](float* dst, const float* src) {
#pragma unroll
        for (int i = 0; i < 8; i++) {
            int id = tid + i * 256;
            int r = id >> 5, c4 = id & 31;
            cp_async16(smem_u32(dst + r * AST + c4 * 4), src + (size_t)r * LDQ + c4 * 4);
        }
    };

    const int wm = wid >> 1;   // 0..3
    const int wn = wid & 1;    // 0..1

    const int sq = tid & 63;
    const int sp = tid >> 6;
    const int qoff = (qbase & 255) + sq;

    wmma::fragment<wmma::accumulator, 16, 16, 8, float> acc_o[2][2];
#pragma unroll
    for (int i = 0; i < 2; i++)
#pragma unroll
        for (int j = 0; j < 2; j++) wmma::fill_fragment(acc_o[i][j], 0.0f);

    load64(shQ, Qp);           CP_COMMIT();
    load64(L0, Kbase);         CP_COMMIT();
    load64(L1, Kbase + (size_t)64 * LDQ);  CP_COMMIT();

    auto st_compute = [&](const float* pa, const float* pb, int ss) {
        const float* abase = ((wm < 2) ? pa : pb) + ((wm & 1) * 32) * AST;
        wmma::fragment<wmma::accumulator, 16, 16, 8, float> accs[2][2];
#pragma unroll
        for (int i = 0; i < 2; i++)
#pragma unroll
            for (int j = 0; j < 2; j++) wmma::fill_fragment(accs[i][j], 0.0f);
#pragma unroll
        for (int kk = 0; kk < 16; kk++) {
            wmma::fragment<wmma::matrix_a, 16, 16, 8, wmma::precision::tf32, wmma::row_major> af[2];
            wmma::fragment<wmma::matrix_b, 16, 16, 8, wmma::precision::tf32, wmma::col_major> bf[2];
#pragma unroll
            for (int i = 0; i < 2; i++)
                wmma::load_matrix_sync(af[i], abase + (i * 16) * AST + kk * 8, AST);
#pragma unroll
            for (int j = 0; j < 2; j++)
                wmma::load_matrix_sync(bf[j], shQ + (wn * 32 + j * 16) * AST + kk * 8, AST);
#pragma unroll
            for (int i = 0; i < 2; i++)
#pragma unroll
                for (int j = 0; j < 2; j++)
                    wmma::mma_sync(accs[i][j], af[i], bf[j], accs[i][j]);
        }
#pragma unroll
        for (int i = 0; i < 2; i++)
#pragma unroll
            for (int j = 0; j < 2; j++)
                wmma::store_matrix_sync(
                    shS + (ss * 128 + wm * 32 + i * 16) * STT + wn * 32 + j * 16,
                    accs[i][j], STT, wmma::mem_row_major);
    };

    auto pv_compute = [&](const float* vb, int v) {
#pragma unroll
        for (int kk = 0; kk < 8; kk++) {
            wmma::fragment<wmma::matrix_a, 16, 16, 8, wmma::precision::tf32, wmma::col_major> af[2];
            wmma::fragment<wmma::matrix_b, 16, 16, 8, wmma::precision::tf32, wmma::row_major> bf[2];
#pragma unroll
            for (int i = 0; i < 2; i++)
                wmma::load_matrix_sync(af[i], vb + (kk * 8) * AST + wm * 32 + i * 16, AST);
#pragma unroll
            for (int j = 0; j < 2; j++)
                wmma::load_matrix_sync(bf[j], shS + (v * 64 + kk * 8) * STT + wn * 32 + j * 16, STT);
#pragma unroll
            for (int i = 0; i < 2; i++)
#pragma unroll
                for (int j = 0; j < 2; j++)
                    wmma::mma_sync(acc_o[i][j], af[i], bf[j], acc_o[i][j]);
        }
    };

    for (int jb = 0; jb <= bi; jb++) {
        const float* Kj = Kbase + (size_t)jb * BSv * LDQ;
        const float* Vj = Vbase + (size_t)jb * BSv * LDQ;
        const bool more = (jb < bi);

        // Phase A: ST1 on (L0, L1); prefetch K3->L2
        CP_WAIT(0);
        __syncthreads();
        load64(L2, Kj + (size_t)128 * LDQ);  CP_COMMIT();
        st_compute(L0, L1, 0);

        // Phase B: ST2 on (L2, L0); K4->L0 (exposed), V1->L1 (hidden)
        __syncthreads();
        load64(L0, Kj + (size_t)192 * LDQ);  CP_COMMIT();
        load64(L1, Vj);                      CP_COMMIT();
        CP_WAIT(1);
        __syncthreads();
        st_compute(L2, L0, 1);

        // Phase C: softmax; V2->L2, V3->L0 (hidden)
        __syncthreads();
        load64(L2, Vj + (size_t)64 * LDQ);   CP_COMMIT();
        load64(L0, Vj + (size_t)128 * LDQ);  CP_COMMIT();
        {
            const bool diag = (jb == bi);
            float sumv = 0.0f;
#pragma unroll 8
            for (int c = 0; c < 64; c++) {
                int key = sp * 64 + c;
                float* addr = shS + key * STT + sq;
                bool masked = diag && (key > qoff);
                float p = masked ? 0.0f : __expf(*addr * ATT_SCALE);
                *addr = p;
                sumv += p;
            }
            shRed[sp * 64 + sq] = sumv;
            __syncthreads();
            if (tid < 64)
                shInv[tid] = 1.0f / (shRed[tid] + shRed[64 + tid] +
                                     shRed[128 + tid] + shRed[192 + tid]);
            __syncthreads();
            float inv = shInv[sq];
#pragma unroll 8
            for (int c = 0; c < 64; c++) {
                float* addr = shS + (sp * 64 + c) * STT + sq;
                *addr = to_tf32(*addr * inv);
            }
        }

        // Phase D: PV1 on L1 (keys 0-63)
        CP_WAIT(2);
        __syncthreads();
        pv_compute(L1, 0);

        // Phase E: PV2 on L2 (keys 64-127); nK2->L1
        CP_WAIT(1);
        __syncthreads();
        if (more) { load64(L1, Kj + (size_t)(BSv + 64) * LDQ); CP_COMMIT(); }
        pv_compute(L2, 1);

        // Phase F: PV3 on L0 (keys 128-191); V4->L2
        CP_WAIT_DYN(more);
        __syncthreads();
        load64(L2, Vj + (size_t)192 * LDQ);  CP_COMMIT();
        pv_compute(L0, 2);

        // Phase G: PV4 on L2 (keys 192-255); nK1->L0
        CP_WAIT(0);
        __syncthreads();
        if (more) { load64(L0, Kj + (size_t)BSv * LDQ); CP_COMMIT(); }
        pv_compute(L2, 3);
    }

    // ---- epilogue: scale, tf32-round, store O^T col-major (== O row-major) ----
    const float invc = 1.0f / ((float)(bi + 1) + 1e-6f);
#pragma unroll
    for (int i = 0; i < 2; i++)
#pragma unroll
        for (int j = 0; j < 2; j++) {
#pragma unroll
            for (int t = 0; t < acc_o[i][j].num_elements; t++)
                acc_o[i][j].x[t] = to_tf32(acc_o[i][j].x[t] * invc);
            wmma::store_matrix_sync(
                g_o + ((size_t)(b * Sv + qbase + wn * 32 + j * 16)) * Hv
                    + h * HDv + wm * 32 + i * 16,
                acc_o[i][j], Hv, wmma::mem_col_major);
        }
}

// ===========================================================================
// launch
// ===========================================================================
extern "C" void kernel_launch(void* const* d_in, const int* in_sizes, int n_in,
                              void* d_out, int out_size)
{
    const float* X  = (const float*)d_in[0];
    const float* Wq = (const float*)d_in[1];
    const float* Wk = (const float*)d_in[2];
    const float* Wv = (const float*)d_in[3];
    const float* Wo = (const float*)d_in[4];
    float* out = (float*)d_out;

    float *qkv, *o, *xr, *wqkv, *wo;
    cudaGetSymbolAddress((void**)&qkv,  g_qkv);
    cudaGetSymbolAddress((void**)&o,    g_o);
    cudaGetSymbolAddress((void**)&xr,   g_xr);
    cudaGetSymbolAddress((void**)&wqkv, g_wqkv);
    cudaGetSymbolAddress((void**)&wo,   g_wo);

    cudaFuncSetAttribute(gemm_pipe, cudaFuncAttributeMaxDynamicSharedMemorySize, GEMM_SMEM);
    cudaFuncSetAttribute(attn_kernel, cudaFuncAttributeMaxDynamicSharedMemorySize, ATTN_SMEM);

    const int nX4 = Mtot * Hv / 4;
    const int nW4 = Hv * Hv / 4;
    round_tf32_k<<<(nX4 + 255) / 256, 256>>>((const float4*)X,  (float4*)xr, nX4);
    round_tf32_k<<<(nW4 + 255) / 256, 256>>>((const float4*)Wq, (float4*)(wqkv), nW4);
    round_tf32_k<<<(nW4 + 255) / 256, 256>>>((const float4*)Wk, (float4*)(wqkv + (size_t)Hv * Hv), nW4);
    round_tf32_k<<<(nW4 + 255) / 256, 256>>>((const float4*)Wv, (float4*)(wqkv + (size_t)2 * Hv * Hv), nW4);
    round_tf32_k<<<(nW4 + 255) / 256, 256>>>((const float4*)Wo, (float4*)wo, nW4);

    // Fused QKV projection: C[4096, 6144] = X @ [Wq;Wk;Wv]^T, one launch
    dim3 gq(LDQ / BN, Mtot / BM);    // (48, 16) = 768 CTAs
    gemm_pipe<<<gq, 256, GEMM_SMEM>>>(xr, wqkv, qkv, Mtot, LDQ, Hv, 1);

    dim3 ag(Sv / QT, NHv, Bv);       // (32, 16, 2)
    attn_kernel<<<ag, 256, ATTN_SMEM>>>();

    dim3 gg(Hv / BN, Mtot / BM);     // (16, 16)
    gemm_pipe<<<gg, 256, GEMM_SMEM>>>(o, wo, out, Mtot, Hv, Hv, 0);
}

// round 15
// speedup vs baseline: 1.0316x; 1.0316x over previous
#include <cuda_runtime.h>
#include <mma.h>
#include <cstdint>
#include <cstddef>

using namespace nvcuda;

#define Bv   2
#define Sv   2048
#define Hv   2048
#define NHv  16
#define HDv  128
#define BSv  256
#define Mtot (Bv * Sv)
#define LDQ  (3 * Hv)             // fused QKV row stride (6144)
#define ATT_SCALE 0.08838834764831843f  // 1/sqrt(128)

// ---------------- scratch (__device__ globals, allocation-free rule) -------
__device__ float g_qkv[(size_t)Mtot * LDQ];   // [4096][6144]: Q | K | V
__device__ float g_o[(size_t)Mtot * Hv];
__device__ float g_xr[(size_t)Mtot * Hv];
__device__ float g_wqkv[(size_t)3 * Hv * Hv]; // Wq rows, Wk rows, Wv rows
__device__ float g_wo[(size_t)Hv * Hv];

// ---------------- helpers ---------------------------------------------------
__device__ __forceinline__ float to_tf32(float x) {
    float y;
    asm("cvt.rna.tf32.f32 %0, %1;" : "=f"(y) : "f"(x));
    return y;
}

__device__ __forceinline__ uint32_t smem_u32(const void* p) {
    uint32_t a;
    asm("{ .reg .u64 t; cvta.to.shared.u64 t, %1; cvt.u32.u64 %0, t; }" : "=r"(a) : "l"(p));
    return a;
}

__device__ __forceinline__ void cp_async16(uint32_t saddr, const void* gptr) {
    asm volatile("cp.async.cg.shared.global [%0], [%1], 16;" :: "r"(saddr), "l"(gptr));
}
#define CP_COMMIT() asm volatile("cp.async.commit_group;")
#define CP_WAIT(n)  asm volatile("cp.async.wait_group %0;" :: "n"(n))

// ---------------- merged rounding pre-pass (one launch) ---------------------
#define NX4 (Mtot * Hv / 4)   // 2,097,152
#define NW4 (Hv * Hv / 4)     // 1,048,576

__global__ void __launch_bounds__(256) round_all_k(
    const float4* __restrict__ X,  const float4* __restrict__ Wq,
    const float4* __restrict__ Wk, const float4* __restrict__ Wv,
    const float4* __restrict__ Wo)
{
    int i = blockIdx.x * 256 + threadIdx.x;
    const float4* s; float4* d; int so, dofs;
    if (i < NX4)                    { s = X;  d = (float4*)g_xr;   so = i;                 dofs = i; }
    else if (i < NX4 + NW4)         { s = Wq; d = (float4*)g_wqkv; so = i - NX4;           dofs = i - NX4; }
    else if (i < NX4 + 2 * NW4)     { s = Wk; d = (float4*)g_wqkv; so = i - NX4 - NW4;     dofs = i - NX4; }
    else if (i < NX4 + 3 * NW4)     { s = Wv; d = (float4*)g_wqkv; so = i - NX4 - 2 * NW4; dofs = i - NX4; }
    else                            { s = Wo; d = (float4*)g_wo;   so = i - NX4 - 3 * NW4; dofs = so; }
    float4 v = s[so];
    v.x = to_tf32(v.x); v.y = to_tf32(v.y);
    v.z = to_tf32(v.z); v.w = to_tf32(v.w);
    d[dofs] = v;
}

// ===========================================================================
// Pipelined tf32 wmma GEMM — R4 configuration (untouched, best measured):
// CTA tile 256x128x32, 8 warps (4x2) with 64x64 warp tiles, 4-stage cp.async.
// ===========================================================================
#define BM 256
#define BN 128
#define BK 32
#define STR 36
#define NSTG 4
#define A_FLTS (BM * STR)
#define B_FLTS (BN * STR)
#define STAGE_FLTS (A_FLTS + B_FLTS)
#define GEMM_SMEM (NSTG * STAGE_FLTS * 4)   // 221184 B -> 1 CTA/SM

__device__ __forceinline__ void stage_load(
    float* stg, const float* __restrict__ Ag, const float* __restrict__ Bg,
    int K, int tid)
{
#pragma unroll
    for (int i = 0; i < 8; i++) {
        int id = tid + i * 256;
        int r = id >> 3, c = id & 7;
        cp_async16(smem_u32(stg + r * STR + c * 4), Ag + (size_t)r * K + c * 4);
    }
#pragma unroll
    for (int i = 0; i < 4; i++) {
        int id = tid + i * 256;
        int r = id >> 3, c = id & 7;
        cp_async16(smem_u32(stg + A_FLTS + r * STR + c * 4), Bg + (size_t)r * K + c * 4);
    }
}

__global__ void __launch_bounds__(256, 1) gemm_pipe(
    const float* __restrict__ A, const float* __restrict__ Bw,
    float* __restrict__ C, int M, int N, int K, int do_round)
{
    extern __shared__ __align__(16) float sm[];

    const int tid = threadIdx.x;
    const int wid = tid >> 5;
    const int m0 = blockIdx.y * BM;
    const int n0 = blockIdx.x * BN;
    const int wm = wid & 3;
    const int wn = wid >> 2;

    const float* Abase = A + (size_t)m0 * K;
    const float* Bbase = Bw + (size_t)n0 * K;
    const int KT = K / BK;

    wmma::fragment<wmma::accumulator, 16, 16, 8, float> acc[4][4];
#pragma unroll
    for (int i = 0; i < 4; i++)
#pragma unroll
        for (int j = 0; j < 4; j++) wmma::fill_fragment(acc[i][j], 0.0f);

#pragma unroll
    for (int t = 0; t < NSTG - 1; t++) {
        stage_load(sm + t * STAGE_FLTS, Abase + t * BK, Bbase + t * BK, K, tid);
        CP_COMMIT();
    }

    for (int kt = 0; kt < KT; kt++) {
        CP_WAIT(NSTG - 2);
        __syncthreads();

        int tn = kt + NSTG - 1;
        if (tn < KT)
            stage_load(sm + (tn % NSTG) * STAGE_FLTS, Abase + (size_t)tn * BK,
                       Bbase + (size_t)tn * BK, K, tid);
        CP_COMMIT();

        const float* sA = sm + (kt % NSTG) * STAGE_FLTS;
        const float* sB = sA + A_FLTS;

#pragma unroll
        for (int kk = 0; kk < 4; kk++) {
            wmma::fragment<wmma::matrix_a, 16, 16, 8, wmma::precision::tf32, wmma::row_major> af[4];
            wmma::fragment<wmma::matrix_b, 16, 16, 8, wmma::precision::tf32, wmma::col_major> bf[4];
#pragma unroll
            for (int i = 0; i < 4; i++)
                wmma::load_matrix_sync(af[i], sA + (wm * 64 + i * 16) * STR + kk * 8, STR);
#pragma unroll
            for (int j = 0; j < 4; j++)
                wmma::load_matrix_sync(bf[j], sB + (wn * 64 + j * 16) * STR + kk * 8, STR);
#pragma unroll
            for (int j = 0; j < 4; j++)
#pragma unroll
                for (int i = 0; i < 4; i++)
                    wmma::mma_sync(acc[i][j], af[i], bf[j], acc[i][j]);
        }
    }

#pragma unroll
    for (int i = 0; i < 4; i++)
#pragma unroll
        for (int j = 0; j < 4; j++) {
            if (do_round) {
#pragma unroll
                for (int t = 0; t < acc[i][j].num_elements; t++)
                    acc[i][j].x[t] = to_tf32(acc[i][j].x[t]);
            }
            wmma::store_matrix_sync(
                C + (size_t)(m0 + wm * 64 + i * 16) * N + n0 + wn * 64 + j * 16,
                acc[i][j], N, wmma::mem_row_major);
        }
}

// ===========================================================================
// Attention, transposed-S (R12 base). Main loop handles full blocks only
// (static, mask-free); the diagonal block is a peeled tail specialized on
// pdiag — skipped ST/PV subtiles carry exactly zero weight.
// ===========================================================================
#define QT  64
#define AST 132
#define STT 68

#define SM_Q   0
#define SM_KV  (QT * AST)
#define KVSZ   (64 * AST)
#define SM_ST  (SM_KV + 3 * KVSZ)
#define SM_RED (SM_ST + 256 * STT)
#define SM_INV (SM_RED + 256)
#define ATTN_SMEM ((SM_INV + 64) * 4)        // 206080 B

__global__ void __launch_bounds__(256) attn_kernel()
{
    extern __shared__ __align__(16) float sm[];
    float* shQ  = sm + SM_Q;
    float* L0   = sm + SM_KV;
    float* L1   = L0 + KVSZ;
    float* L2   = L1 + KVSZ;
    float* shS  = sm + SM_ST;
    float* shRed = sm + SM_RED;
    float* shInv = sm + SM_INV;

    const int tid = threadIdx.x;
    const int wid = tid >> 5;
    const int qt = gridDim.x - 1 - blockIdx.x;   // expensive tiles first
    const int h  = blockIdx.y;
    const int b  = blockIdx.z;
    const int qbase = qt * QT;
    const int bi = qbase >> 8;
    const int pdiag = (qbase >> 6) & 3;

    const float* Qp    = g_qkv + ((size_t)b * Sv + qbase) * LDQ + h * HDv;
    const float* Kbase = g_qkv + ((size_t)b * Sv) * LDQ + Hv + h * HDv;
    const float* Vbase = g_qkv + ((size_t)b * Sv) * LDQ + 2 * Hv + h * HDv;

    auto load64 = [&](float* dst, const float* src) {
#pragma unroll
        for (int i = 0; i < 8; i++) {
            int id = tid + i * 256;
            int r = id >> 5, c4 = id & 31;
            cp_async16(smem_u32(dst + r * AST + c4 * 4), src + (size_t)r * LDQ + c4 * 4);
        }
    };

    const int wm = wid >> 1;   // 0..3
    const int wn = wid & 1;    // 0..1

    const int sq = tid & 63;
    const int sp = tid >> 6;
    const int qoff = (qbase & 255) + sq;

    wmma::fragment<wmma::accumulator, 16, 16, 8, float> acc_o[2][2];
#pragma unroll
    for (int i = 0; i < 2; i++)
#pragma unroll
        for (int j = 0; j < 2; j++) wmma::fill_fragment(acc_o[i][j], 0.0f);

    load64(shQ, Qp);           CP_COMMIT();
    load64(L0, Kbase);         CP_COMMIT();
    load64(L1, Kbase + (size_t)64 * LDQ);  CP_COMMIT();

    auto st_compute = [&](const float* pa, const float* pb, int ss) {
        const float* abase = ((wm < 2) ? pa : pb) + ((wm & 1) * 32) * AST;
        wmma::fragment<wmma::accumulator, 16, 16, 8, float> accs[2][2];
#pragma unroll
        for (int i = 0; i < 2; i++)
#pragma unroll
            for (int j = 0; j < 2; j++) wmma::fill_fragment(accs[i][j], 0.0f);
#pragma unroll
        for (int kk = 0; kk < 16; kk++) {
            wmma::fragment<wmma::matrix_a, 16, 16, 8, wmma::precision::tf32, wmma::row_major> af[2];
            wmma::fragment<wmma::matrix_b, 16, 16, 8, wmma::precision::tf32, wmma::col_major> bf[2];
#pragma unroll
            for (int i = 0; i < 2; i++)
                wmma::load_matrix_sync(af[i], abase + (i * 16) * AST + kk * 8, AST);
#pragma unroll
            for (int j = 0; j < 2; j++)
                wmma::load_matrix_sync(bf[j], shQ + (wn * 32 + j * 16) * AST + kk * 8, AST);
#pragma unroll
            for (int i = 0; i < 2; i++)
#pragma unroll
                for (int j = 0; j < 2; j++)
                    wmma::mma_sync(accs[i][j], af[i], bf[j], accs[i][j]);
        }
#pragma unroll
        for (int i = 0; i < 2; i++)
#pragma unroll
            for (int j = 0; j < 2; j++)
                wmma::store_matrix_sync(
                    shS + (ss * 128 + wm * 32 + i * 16) * STT + wn * 32 + j * 16,
                    accs[i][j], STT, wmma::mem_row_major);
    };

    auto pv_compute = [&](const float* vb, int v) {
#pragma unroll
        for (int kk = 0; kk < 8; kk++) {
            wmma::fragment<wmma::matrix_a, 16, 16, 8, wmma::precision::tf32, wmma::col_major> af[2];
            wmma::fragment<wmma::matrix_b, 16, 16, 8, wmma::precision::tf32, wmma::row_major> bf[2];
#pragma unroll
            for (int i = 0; i < 2; i++)
                wmma::load_matrix_sync(af[i], vb + (kk * 8) * AST + wm * 32 + i * 16, AST);
#pragma unroll
            for (int j = 0; j < 2; j++)
                wmma::load_matrix_sync(bf[j], shS + (v * 64 + kk * 8) * STT + wn * 32 + j * 16, STT);
#pragma unroll
            for (int i = 0; i < 2; i++)
#pragma unroll
                for (int j = 0; j < 2; j++)
                    wmma::mma_sync(acc_o[i][j], af[i], bf[j], acc_o[i][j]);
        }
    };

    // mask-free softmax (main loop: off-diagonal blocks)
    auto softmax_full = [&]() {
        __syncthreads();
        float sumv = 0.0f;
#pragma unroll 8
        for (int c = 0; c < 64; c++) {
            float* addr = shS + (sp * 64 + c) * STT + sq;
            float p = __expf(*addr * ATT_SCALE);
            *addr = p;
            sumv += p;
        }
        shRed[sp * 64 + sq] = sumv;
        __syncthreads();
        if (tid < 64)
            shInv[tid] = 1.0f / (shRed[tid] + shRed[64 + tid] +
                                 shRed[128 + tid] + shRed[192 + tid]);
        __syncthreads();
        float inv = shInv[sq];
#pragma unroll 8
        for (int c = 0; c < 64; c++) {
            float* addr = shS + (sp * 64 + c) * STT + sq;
            *addr = to_tf32(*addr * inv);
        }
    };

    // masked softmax for the diagonal block; quarters beyond pd skip work
    auto softmax_diag = [&](int pd) {
        __syncthreads();
        float sumv = 0.0f;
        if (sp <= pd) {
#pragma unroll 8
            for (int c = 0; c < 64; c++) {
                int key = sp * 64 + c;
                float* addr = shS + key * STT + sq;
                float p = (key > qoff) ? 0.0f : __expf(*addr * ATT_SCALE);
                *addr = p;
                sumv += p;
            }
        }
        shRed[sp * 64 + sq] = sumv;
        __syncthreads();
        if (tid < 64)
            shInv[tid] = 1.0f / (shRed[tid] + shRed[64 + tid] +
                                 shRed[128 + tid] + shRed[192 + tid]);
        __syncthreads();
        float inv = shInv[sq];
        if (sp <= pd) {
#pragma unroll 8
            for (int c = 0; c < 64; c++) {
                float* addr = shS + (sp * 64 + c) * STT + sq;
                *addr = to_tf32(*addr * inv);
            }
        }
    };

    // ======== main loop: full (off-diagonal) blocks, fully static ========
    for (int jb = 0; jb < bi; jb++) {
        const float* Kj = Kbase + (size_t)jb * BSv * LDQ;
        const float* Vj = Vbase + (size_t)jb * BSv * LDQ;

        CP_WAIT(0);
        __syncthreads();
        load64(L2, Kj + (size_t)128 * LDQ);  CP_COMMIT();
        st_compute(L0, L1, 0);

        __syncthreads();
        load64(L0, Kj + (size_t)192 * LDQ);  CP_COMMIT();
        load64(L1, Vj);                      CP_COMMIT();
        CP_WAIT(1);
        __syncthreads();
        st_compute(L2, L0, 1);

        __syncthreads();
        load64(L2, Vj + (size_t)64 * LDQ);   CP_COMMIT();
        load64(L0, Vj + (size_t)128 * LDQ);  CP_COMMIT();
        softmax_full();

        CP_WAIT(2);
        __syncthreads();
        pv_compute(L1, 0);

        CP_WAIT(1);
        __syncthreads();
        load64(L1, Kj + (size_t)(BSv + 64) * LDQ); CP_COMMIT();   // nK2
        pv_compute(L2, 1);

        CP_WAIT(1);
        __syncthreads();
        load64(L2, Vj + (size_t)192 * LDQ);  CP_COMMIT();
        pv_compute(L0, 2);

        CP_WAIT(0);
        __syncthreads();
        load64(L0, Kj + (size_t)BSv * LDQ);  CP_COMMIT();         // nK1
        pv_compute(L2, 3);
    }

    // ======== diagonal tail (jb = bi), specialized on pdiag ========
    {
        const float* Kj = Kbase + (size_t)bi * BSv * LDQ;
        const float* Vj = Vbase + (size_t)bi * BSv * LDQ;

        if (pdiag == 0) {
            CP_WAIT(0);
            __syncthreads();
            load64(L2, Vj);  CP_COMMIT();                  // V1
            st_compute(L0, L1, 0);                         // keys 0-127 (64-127 masked)
            softmax_diag(0);
            CP_WAIT(0);
            __syncthreads();
            pv_compute(L2, 0);
        } else if (pdiag == 1) {
            CP_WAIT(0);
            __syncthreads();
            load64(L2, Vj);  CP_COMMIT();                  // V1
            st_compute(L0, L1, 0);
            __syncthreads();                               // ST1 done -> L0 free
            load64(L0, Vj + (size_t)64 * LDQ);  CP_COMMIT();  // V2
            softmax_diag(1);
            CP_WAIT(1);
            __syncthreads();
            pv_compute(L2, 0);
            CP_WAIT(0);
            __syncthreads();
            pv_compute(L0, 1);
        } else if (pdiag == 2) {
            CP_WAIT(0);
            __syncthreads();
            load64(L2, Kj + (size_t)128 * LDQ);  CP_COMMIT();  // K3
            st_compute(L0, L1, 0);
            __syncthreads();                               // ST1 done -> L0,L1 free
            load64(L0, Vj);                      CP_COMMIT();  // V1
            load64(L1, Vj + (size_t)64 * LDQ);   CP_COMMIT();  // V2
            CP_WAIT(2);                                    // K3 done
            __syncthreads();
            st_compute(L2, L2, 1);                         // keys 128-191 valid; 192-255 masked
            __syncthreads();                               // ST2 done -> L2 free
            load64(L2, Vj + (size_t)128 * LDQ);  CP_COMMIT();  // V3
            softmax_diag(2);
            CP_WAIT(2);
            __syncthreads();
            pv_compute(L0, 0);
            CP_WAIT(1);
            __syncthreads();
            pv_compute(L1, 1);
            CP_WAIT(0);
            __syncthreads();
            pv_compute(L2, 2);
        } else {
            CP_WAIT(0);
            __syncthreads();
            load64(L2, Kj + (size_t)128 * LDQ);  CP_COMMIT();  // K3
            st_compute(L0, L1, 0);
            __syncthreads();
            load64(L0, Kj + (size_t)192 * LDQ);  CP_COMMIT();  // K4
            load64(L1, Vj);                      CP_COMMIT();  // V1
            CP_WAIT(1);                                    // K3,K4 done
            __syncthreads();
            st_compute(L2, L0, 1);
            __syncthreads();
            load64(L2, Vj + (size_t)64 * LDQ);   CP_COMMIT();  // V2
            load64(L0, Vj + (size_t)128 * LDQ);  CP_COMMIT();  // V3
            softmax_diag(3);
            CP_WAIT(2);
            __syncthreads();
            pv_compute(L1, 0);
            CP_WAIT(1);
            __syncthreads();
            pv_compute(L2, 1);
            CP_WAIT(0);
            __syncthreads();
            load64(L2, Vj + (size_t)192 * LDQ);  CP_COMMIT();  // V4
            pv_compute(L0, 2);
            CP_WAIT(0);
            __syncthreads();
            pv_compute(L2, 3);
        }
    }

    // ---- epilogue: scale, tf32-round, store O^T col-major (== O row-major) ----
    const float invc = 1.0f / ((float)(bi + 1) + 1e-6f);
#pragma unroll
    for (int i = 0; i < 2; i++)
#pragma unroll
        for (int j = 0; j < 2; j++) {
#pragma unroll
            for (int t = 0; t < acc_o[i][j].num_elements; t++)
                acc_o[i][j].x[t] = to_tf32(acc_o[i][j].x[t] * invc);
            wmma::store_matrix_sync(
                g_o + ((size_t)(b * Sv + qbase + wn * 32 + j * 16)) * Hv
                    + h * HDv + wm * 32 + i * 16,
                acc_o[i][j], Hv, wmma::mem_col_major);
        }
}

// ===========================================================================
// launch
// ===========================================================================
extern "C" void kernel_launch(void* const* d_in, const int* in_sizes, int n_in,
                              void* d_out, int out_size)
{
    const float* X  = (const float*)d_in[0];
    const float* Wq = (const float*)d_in[1];
    const float* Wk = (const float*)d_in[2];
    const float* Wv = (const float*)d_in[3];
    const float* Wo = (const float*)d_in[4];
    float* out = (float*)d_out;

    float *qkv, *o, *xr, *wqkv, *wo;
    cudaGetSymbolAddress((void**)&qkv,  g_qkv);
    cudaGetSymbolAddress((void**)&o,    g_o);
    cudaGetSymbolAddress((void**)&xr,   g_xr);
    cudaGetSymbolAddress((void**)&wqkv, g_wqkv);
    cudaGetSymbolAddress((void**)&wo,   g_wo);

    cudaFuncSetAttribute(gemm_pipe, cudaFuncAttributeMaxDynamicSharedMemorySize, GEMM_SMEM);
    cudaFuncSetAttribute(attn_kernel, cudaFuncAttributeMaxDynamicSharedMemorySize, ATTN_SMEM);

    // single-launch tf32 rounding of X + Wq|Wk|Wv (into g_wqkv) + Wo
    round_all_k<<<(NX4 + 4 * NW4) / 256, 256>>>(
        (const float4*)X, (const float4*)Wq, (const float4*)Wk,
        (const float4*)Wv, (const float4*)Wo);

    // Fused QKV projection: [4096, 6144] = X @ [Wq;Wk;Wv]^T
    dim3 gq(LDQ / BN, Mtot / BM);    // (48, 16) = 768 CTAs
    gemm_pipe<<<gq, 256, GEMM_SMEM>>>(xr, wqkv, qkv, Mtot, LDQ, Hv, 1);

    dim3 ag(Sv / QT, NHv, Bv);       // (32, 16, 2)
    attn_kernel<<<ag, 256, ATTN_SMEM>>>();

    dim3 gg(Hv / BN, Mtot / BM);     // (16, 16)
    gemm_pipe<<<gg, 256, GEMM_SMEM>>>(o, wo, out, Mtot, Hv, Hv, 0);
}

// round 16
// speedup vs baseline: 1.0328x; 1.0012x over previous
#include <cuda_runtime.h>
#include <mma.h>
#include <cstdint>
#include <cstddef>

using namespace nvcuda;

#define Bv   2
#define Sv   2048
#define Hv   2048
#define NHv  16
#define HDv  128
#define BSv  256
#define Mtot (Bv * Sv)
#define LDQ  (3 * Hv)             // fused QKV row stride (6144)
#define ATT_SCALE 0.08838834764831843f  // 1/sqrt(128)

// ---------------- scratch (__device__ globals, allocation-free rule) -------
__device__ float g_qkv[(size_t)Mtot * LDQ];   // [4096][6144]: Q | K | V
__device__ float g_o[(size_t)Mtot * Hv];
__device__ float g_xr[(size_t)Mtot * Hv];
__device__ float g_wqkv[(size_t)3 * Hv * Hv]; // Wq rows, Wk rows, Wv rows
__device__ float g_wo[(size_t)Hv * Hv];

// ---------------- helpers ---------------------------------------------------
__device__ __forceinline__ float to_tf32(float x) {
    float y;
    asm("cvt.rna.tf32.f32 %0, %1;" : "=f"(y) : "f"(x));
    return y;
}

__device__ __forceinline__ uint32_t smem_u32(const void* p) {
    uint32_t a;
    asm("{ .reg .u64 t; cvta.to.shared.u64 t, %1; cvt.u32.u64 %0, t; }" : "=r"(a) : "l"(p));
    return a;
}

__device__ __forceinline__ void cp_async16(uint32_t saddr, const void* gptr) {
    asm volatile("cp.async.cg.shared.global [%0], [%1], 16;" :: "r"(saddr), "l"(gptr));
}
#define CP_COMMIT() asm volatile("cp.async.commit_group;")
#define CP_WAIT(n)  asm volatile("cp.async.wait_group %0;" :: "n"(n))

// ---------------- merged rounding pre-pass (one launch) ---------------------
#define NX4 (Mtot * Hv / 4)   // 2,097,152
#define NW4 (Hv * Hv / 4)     // 1,048,576

__global__ void __launch_bounds__(256) round_all_k(
    const float4* __restrict__ X,  const float4* __restrict__ Wq,
    const float4* __restrict__ Wk, const float4* __restrict__ Wv,
    const float4* __restrict__ Wo)
{
    int i = blockIdx.x * 256 + threadIdx.x;
    const float4* s; float4* d; int so, dofs;
    if (i < NX4)                    { s = X;  d = (float4*)g_xr;   so = i;                 dofs = i; }
    else if (i < NX4 + NW4)         { s = Wq; d = (float4*)g_wqkv; so = i - NX4;           dofs = i - NX4; }
    else if (i < NX4 + 2 * NW4)     { s = Wk; d = (float4*)g_wqkv; so = i - NX4 - NW4;     dofs = i - NX4; }
    else if (i < NX4 + 3 * NW4)     { s = Wv; d = (float4*)g_wqkv; so = i - NX4 - 2 * NW4; dofs = i - NX4; }
    else                            { s = Wo; d = (float4*)g_wo;   so = i - NX4 - 3 * NW4; dofs = so; }
    float4 v = s[so];
    v.x = to_tf32(v.x); v.y = to_tf32(v.y);
    v.z = to_tf32(v.z); v.w = to_tf32(v.w);
    d[dofs] = v;
}

// ===========================================================================
// Pipelined tf32 wmma GEMM — R4 configuration (untouched, best measured):
// CTA tile 256x128x32, 8 warps (4x2) with 64x64 warp tiles, 4-stage cp.async.
// ===========================================================================
#define BM 256
#define BN 128
#define BK 32
#define STR 36
#define NSTG 4
#define A_FLTS (BM * STR)
#define B_FLTS (BN * STR)
#define STAGE_FLTS (A_FLTS + B_FLTS)
#define GEMM_SMEM (NSTG * STAGE_FLTS * 4)   // 221184 B -> 1 CTA/SM

__device__ __forceinline__ void stage_load(
    float* stg, const float* __restrict__ Ag, const float* __restrict__ Bg,
    int K, int tid)
{
#pragma unroll
    for (int i = 0; i < 8; i++) {
        int id = tid + i * 256;
        int r = id >> 3, c = id & 7;
        cp_async16(smem_u32(stg + r * STR + c * 4), Ag + (size_t)r * K + c * 4);
    }
#pragma unroll
    for (int i = 0; i < 4; i++) {
        int id = tid + i * 256;
        int r = id >> 3, c = id & 7;
        cp_async16(smem_u32(stg + A_FLTS + r * STR + c * 4), Bg + (size_t)r * K + c * 4);
    }
}

__global__ void __launch_bounds__(256, 1) gemm_pipe(
    const float* __restrict__ A, const float* __restrict__ Bw,
    float* __restrict__ C, int M, int N, int K, int do_round)
{
    extern __shared__ __align__(16) float sm[];

    const int tid = threadIdx.x;
    const int wid = tid >> 5;
    const int m0 = blockIdx.y * BM;
    const int n0 = blockIdx.x * BN;
    const int wm = wid & 3;
    const int wn = wid >> 2;

    const float* Abase = A + (size_t)m0 * K;
    const float* Bbase = Bw + (size_t)n0 * K;
    const int KT = K / BK;

    wmma::fragment<wmma::accumulator, 16, 16, 8, float> acc[4][4];
#pragma unroll
    for (int i = 0; i < 4; i++)
#pragma unroll
        for (int j = 0; j < 4; j++) wmma::fill_fragment(acc[i][j], 0.0f);

#pragma unroll
    for (int t = 0; t < NSTG - 1; t++) {
        stage_load(sm + t * STAGE_FLTS, Abase + t * BK, Bbase + t * BK, K, tid);
        CP_COMMIT();
    }

    for (int kt = 0; kt < KT; kt++) {
        CP_WAIT(NSTG - 2);
        __syncthreads();

        int tn = kt + NSTG - 1;
        if (tn < KT)
            stage_load(sm + (tn % NSTG) * STAGE_FLTS, Abase + (size_t)tn * BK,
                       Bbase + (size_t)tn * BK, K, tid);
        CP_COMMIT();

        const float* sA = sm + (kt % NSTG) * STAGE_FLTS;
        const float* sB = sA + A_FLTS;

#pragma unroll
        for (int kk = 0; kk < 4; kk++) {
            wmma::fragment<wmma::matrix_a, 16, 16, 8, wmma::precision::tf32, wmma::row_major> af[4];
            wmma::fragment<wmma::matrix_b, 16, 16, 8, wmma::precision::tf32, wmma::col_major> bf[4];
#pragma unroll
            for (int i = 0; i < 4; i++)
                wmma::load_matrix_sync(af[i], sA + (wm * 64 + i * 16) * STR + kk * 8, STR);
#pragma unroll
            for (int j = 0; j < 4; j++)
                wmma::load_matrix_sync(bf[j], sB + (wn * 64 + j * 16) * STR + kk * 8, STR);
#pragma unroll
            for (int j = 0; j < 4; j++)
#pragma unroll
                for (int i = 0; i < 4; i++)
                    wmma::mma_sync(acc[i][j], af[i], bf[j], acc[i][j]);
        }
    }

#pragma unroll
    for (int i = 0; i < 4; i++)
#pragma unroll
        for (int j = 0; j < 4; j++) {
            if (do_round) {
#pragma unroll
                for (int t = 0; t < acc[i][j].num_elements; t++)
                    acc[i][j].x[t] = to_tf32(acc[i][j].x[t]);
            }
            wmma::store_matrix_sync(
                C + (size_t)(m0 + wm * 64 + i * 16) * N + n0 + wn * 64 + j * 16,
                acc[i][j], N, wmma::mem_row_major);
        }
}

// ===========================================================================
// Attention, transposed-S. Main loop: mask-free full blocks with the exp of
// keys 0-127 FUSED into the ST2 mma loop (MUFU overlaps tensor pipe); keys
// 128-255 exp'd in phase C. Diagonal block is a peeled specialized tail.
// ===========================================================================
#define QT  64
#define AST 132
#define STT 68

#define SM_Q   0
#define SM_KV  (QT * AST)
#define KVSZ   (64 * AST)
#define SM_ST  (SM_KV + 3 * KVSZ)
#define SM_RED (SM_ST + 256 * STT)           // 512 partials: [half][quarter][q]
#define SM_INV (SM_RED + 512)
#define ATTN_SMEM ((SM_INV + 64) * 4)        // 207360 B

__global__ void __launch_bounds__(256) attn_kernel()
{
    extern __shared__ __align__(16) float sm[];
    float* shQ  = sm + SM_Q;
    float* L0   = sm + SM_KV;
    float* L1   = L0 + KVSZ;
    float* L2   = L1 + KVSZ;
    float* shS  = sm + SM_ST;
    float* shRed = sm + SM_RED;
    float* shInv = sm + SM_INV;

    const int tid = threadIdx.x;
    const int wid = tid >> 5;
    const int qt = gridDim.x - 1 - blockIdx.x;   // expensive tiles first
    const int h  = blockIdx.y;
    const int b  = blockIdx.z;
    const int qbase = qt * QT;
    const int bi = qbase >> 8;
    const int pdiag = (qbase >> 6) & 3;

    const float* Qp    = g_qkv + ((size_t)b * Sv + qbase) * LDQ + h * HDv;
    const float* Kbase = g_qkv + ((size_t)b * Sv) * LDQ + Hv + h * HDv;
    const float* Vbase = g_qkv + ((size_t)b * Sv) * LDQ + 2 * Hv + h * HDv;

    auto load64 = [&](float* dst, const float* src) {
#pragma unroll
        for (int i = 0; i < 8; i++) {
            int id = tid + i * 256;
            int r = id >> 5, c4 = id & 31;
            cp_async16(smem_u32(dst + r * AST + c4 * 4), src + (size_t)r * LDQ + c4 * 4);
        }
    };

    const int wm = wid >> 1;   // 0..3
    const int wn = wid & 1;    // 0..1

    const int sq = tid & 63;   // query (scale pass / diag softmax)
    const int sp = tid >> 6;   // key quarter
    const int qoff = (qbase & 255) + sq;

    wmma::fragment<wmma::accumulator, 16, 16, 8, float> acc_o[2][2];
#pragma unroll
    for (int i = 0; i < 2; i++)
#pragma unroll
        for (int j = 0; j < 2; j++) wmma::fill_fragment(acc_o[i][j], 0.0f);

    load64(shQ, Qp);           CP_COMMIT();
    load64(L0, Kbase);         CP_COMMIT();
    load64(L1, Kbase + (size_t)64 * LDQ);  CP_COMMIT();

    auto st_compute = [&](const float* pa, const float* pb, int ss) {
        const float* abase = ((wm < 2) ? pa : pb) + ((wm & 1) * 32) * AST;
        wmma::fragment<wmma::accumulator, 16, 16, 8, float> accs[2][2];
#pragma unroll
        for (int i = 0; i < 2; i++)
#pragma unroll
            for (int j = 0; j < 2; j++) wmma::fill_fragment(accs[i][j], 0.0f);
#pragma unroll
        for (int kk = 0; kk < 16; kk++) {
            wmma::fragment<wmma::matrix_a, 16, 16, 8, wmma::precision::tf32, wmma::row_major> af[2];
            wmma::fragment<wmma::matrix_b, 16, 16, 8, wmma::precision::tf32, wmma::col_major> bf[2];
#pragma unroll
            for (int i = 0; i < 2; i++)
                wmma::load_matrix_sync(af[i], abase + (i * 16) * AST + kk * 8, AST);
#pragma unroll
            for (int j = 0; j < 2; j++)
                wmma::load_matrix_sync(bf[j], shQ + (wn * 32 + j * 16) * AST + kk * 8, AST);
#pragma unroll
            for (int i = 0; i < 2; i++)
#pragma unroll
                for (int j = 0; j < 2; j++)
                    wmma::mma_sync(accs[i][j], af[i], bf[j], accs[i][j]);
        }
#pragma unroll
        for (int i = 0; i < 2; i++)
#pragma unroll
            for (int j = 0; j < 2; j++)
                wmma::store_matrix_sync(
                    shS + (ss * 128 + wm * 32 + i * 16) * STT + wn * 32 + j * 16,
                    accs[i][j], STT, wmma::mem_row_major);
    };

    // ST2 mma (keys 128-255) with exp of keys 0-127 interleaved per kk:
    // tensor and MUFU pipes overlap instead of serializing.
    auto st2_fused_exp = [&](const float* pa, const float* pb) {
        const float* abase = ((wm < 2) ? pa : pb) + ((wm & 1) * 32) * AST;
        wmma::fragment<wmma::accumulator, 16, 16, 8, float> accs[2][2];
#pragma unroll
        for (int i = 0; i < 2; i++)
#pragma unroll
            for (int j = 0; j < 2; j++) wmma::fill_fragment(accs[i][j], 0.0f);
        const int eq = tid & 63;        // query
        const int ekq = tid >> 6;       // quarter of keys 0-127 (32 rows each)
        float sumv = 0.0f;
#pragma unroll
        for (int kk = 0; kk < 16; kk++) {
            wmma::fragment<wmma::matrix_a, 16, 16, 8, wmma::precision::tf32, wmma::row_major> af[2];
            wmma::fragment<wmma::matrix_b, 16, 16, 8, wmma::precision::tf32, wmma::col_major> bf[2];
#pragma unroll
            for (int i = 0; i < 2; i++)
                wmma::load_matrix_sync(af[i], abase + (i * 16) * AST + kk * 8, AST);
#pragma unroll
            for (int j = 0; j < 2; j++)
                wmma::load_matrix_sync(bf[j], shQ + (wn * 32 + j * 16) * AST + kk * 8, AST);
#pragma unroll
            for (int i = 0; i < 2; i++)
#pragma unroll
                for (int j = 0; j < 2; j++)
                    wmma::mma_sync(accs[i][j], af[i], bf[j], accs[i][j]);
            // 2 exps of keys 0-127 (rows written by ST1, barrier-protected)
#pragma unroll
            for (int e = 0; e < 2; e++) {
                int key = ekq * 32 + kk * 2 + e;
                float* addr = shS + key * STT + eq;
                float p = __expf(*addr * ATT_SCALE);
                *addr = p;
                sumv += p;
            }
        }
        shRed[ekq * 64 + eq] = sumv;    // half 0 partials
#pragma unroll
        for (int i = 0; i < 2; i++)
#pragma unroll
            for (int j = 0; j < 2; j++)
                wmma::store_matrix_sync(
                    shS + (128 + wm * 32 + i * 16) * STT + wn * 32 + j * 16,
                    accs[i][j], STT, wmma::mem_row_major);
    };

    auto pv_compute = [&](const float* vb, int v) {
#pragma unroll
        for (int kk = 0; kk < 8; kk++) {
            wmma::fragment<wmma::matrix_a, 16, 16, 8, wmma::precision::tf32, wmma::col_major> af[2];
            wmma::fragment<wmma::matrix_b, 16, 16, 8, wmma::precision::tf32, wmma::row_major> bf[2];
#pragma unroll
            for (int i = 0; i < 2; i++)
                wmma::load_matrix_sync(af[i], vb + (kk * 8) * AST + wm * 32 + i * 16, AST);
#pragma unroll
            for (int j = 0; j < 2; j++)
                wmma::load_matrix_sync(bf[j], shS + (v * 64 + kk * 8) * STT + wn * 32 + j * 16, STT);
#pragma unroll
            for (int i = 0; i < 2; i++)
#pragma unroll
                for (int j = 0; j < 2; j++)
                    wmma::mma_sync(acc_o[i][j], af[i], bf[j], acc_o[i][j]);
        }
    };

    // phase C of main loop: exp keys 128-255, combine 8 partials, scale all
    auto softmax_finish = [&]() {
        const int eq = tid & 63;
        const int ekq = tid >> 6;
        float sumv = 0.0f;
#pragma unroll 8
        for (int c = 0; c < 32; c++) {
            int key = 128 + ekq * 32 + c;
            float* addr = shS + key * STT + eq;
            float p = __expf(*addr * ATT_SCALE);
            *addr = p;
            sumv += p;
        }
        shRed[256 + ekq * 64 + eq] = sumv;   // half 1 partials
        __syncthreads();
        if (tid < 64) {
            float s = shRed[tid]       + shRed[64 + tid]  + shRed[128 + tid] + shRed[192 + tid]
                    + shRed[256 + tid] + shRed[320 + tid] + shRed[384 + tid] + shRed[448 + tid];
            shInv[tid] = 1.0f / s;
        }
        __syncthreads();
        float inv = shInv[sq];
#pragma unroll 8
        for (int c = 0; c < 64; c++) {
            float* addr = shS + (sp * 64 + c) * STT + sq;
            *addr = to_tf32(*addr * inv);
        }
    };

    // masked single-pass softmax for the diagonal tail
    auto softmax_diag = [&](int pd) {
        __syncthreads();
        float sumv = 0.0f;
        if (sp <= pd) {
#pragma unroll 8
            for (int c = 0; c < 64; c++) {
                int key = sp * 64 + c;
                float* addr = shS + key * STT + sq;
                float p = (key > qoff) ? 0.0f : __expf(*addr * ATT_SCALE);
                *addr = p;
                sumv += p;
            }
        }
        shRed[sp * 64 + sq] = sumv;
        __syncthreads();
        if (tid < 64)
            shInv[tid] = 1.0f / (shRed[tid] + shRed[64 + tid] +
                                 shRed[128 + tid] + shRed[192 + tid]);
        __syncthreads();
        float inv = shInv[sq];
        if (sp <= pd) {
#pragma unroll 8
            for (int c = 0; c < 64; c++) {
                float* addr = shS + (sp * 64 + c) * STT + sq;
                *addr = to_tf32(*addr * inv);
            }
        }
    };

    // ======== main loop: full (off-diagonal) blocks, fully static ========
    for (int jb = 0; jb < bi; jb++) {
        const float* Kj = Kbase + (size_t)jb * BSv * LDQ;
        const float* Vj = Vbase + (size_t)jb * BSv * LDQ;

        CP_WAIT(0);
        __syncthreads();
        load64(L2, Kj + (size_t)128 * LDQ);  CP_COMMIT();
        st_compute(L0, L1, 0);

        __syncthreads();
        load64(L0, Kj + (size_t)192 * LDQ);  CP_COMMIT();
        load64(L1, Vj);                      CP_COMMIT();
        CP_WAIT(1);
        __syncthreads();
        st2_fused_exp(L2, L0);               // ST2 mma + exp(keys 0-127)

        __syncthreads();
        load64(L2, Vj + (size_t)64 * LDQ);   CP_COMMIT();
        load64(L0, Vj + (size_t)128 * LDQ);  CP_COMMIT();
        softmax_finish();

        CP_WAIT(2);
        __syncthreads();
        pv_compute(L1, 0);

        CP_WAIT(1);
        __syncthreads();
        load64(L1, Kj + (size_t)(BSv + 64) * LDQ); CP_COMMIT();   // nK2
        pv_compute(L2, 1);

        CP_WAIT(1);
        __syncthreads();
        load64(L2, Vj + (size_t)192 * LDQ);  CP_COMMIT();
        pv_compute(L0, 2);

        CP_WAIT(0);
        __syncthreads();
        load64(L0, Kj + (size_t)BSv * LDQ);  CP_COMMIT();         // nK1
        pv_compute(L2, 3);
    }

    // ======== diagonal tail (jb = bi), specialized on pdiag ========
    {
        const float* Kj = Kbase + (size_t)bi * BSv * LDQ;
        const float* Vj = Vbase + (size_t)bi * BSv * LDQ;

        if (pdiag == 0) {
            CP_WAIT(0);
            __syncthreads();
            load64(L2, Vj);  CP_COMMIT();                  // V1
            st_compute(L0, L1, 0);                         // keys 0-127 (64-127 masked)
            softmax_diag(0);
            CP_WAIT(0);
            __syncthreads();
            pv_compute(L2, 0);
        } else if (pdiag == 1) {
            CP_WAIT(0);
            __syncthreads();
            load64(L2, Vj);  CP_COMMIT();                  // V1
            st_compute(L0, L1, 0);
            __syncthreads();                               // ST1 done -> L0 free
            load64(L0, Vj + (size_t)64 * LDQ);  CP_COMMIT();  // V2
            softmax_diag(1);
            CP_WAIT(1);
            __syncthreads();
            pv_compute(L2, 0);
            CP_WAIT(0);
            __syncthreads();
            pv_compute(L0, 1);
        } else if (pdiag == 2) {
            CP_WAIT(0);
            __syncthreads();
            load64(L2, Kj + (size_t)128 * LDQ);  CP_COMMIT();  // K3
            st_compute(L0, L1, 0);
            __syncthreads();                               // ST1 done -> L0,L1 free
            load64(L0, Vj);                      CP_COMMIT();  // V1
            load64(L1, Vj + (size_t)64 * LDQ);   CP_COMMIT();  // V2
            CP_WAIT(2);                                    // K3 done
            __syncthreads();
            st_compute(L2, L2, 1);                         // keys 128-191 valid; 192-255 masked
            __syncthreads();                               // ST2 done -> L2 free
            load64(L2, Vj + (size_t)128 * LDQ);  CP_COMMIT();  // V3
            softmax_diag(2);
            CP_WAIT(2);
            __syncthreads();
            pv_compute(L0, 0);
            CP_WAIT(1);
            __syncthreads();
            pv_compute(L1, 1);
            CP_WAIT(0);
            __syncthreads();
            pv_compute(L2, 2);
        } else {
            CP_WAIT(0);
            __syncthreads();
            load64(L2, Kj + (size_t)128 * LDQ);  CP_COMMIT();  // K3
            st_compute(L0, L1, 0);
            __syncthreads();
            load64(L0, Kj + (size_t)192 * LDQ);  CP_COMMIT();  // K4
            load64(L1, Vj);                      CP_COMMIT();  // V1
            CP_WAIT(1);                                    // K3,K4 done
            __syncthreads();
            st_compute(L2, L0, 1);
            __syncthreads();
            load64(L2, Vj + (size_t)64 * LDQ);   CP_COMMIT();  // V2
            load64(L0, Vj + (size_t)128 * LDQ);  CP_COMMIT();  // V3
            softmax_diag(3);
            CP_WAIT(2);
            __syncthreads();
            pv_compute(L1, 0);
            CP_WAIT(1);
            __syncthreads();
            pv_compute(L2, 1);
            CP_WAIT(0);
            __syncthreads();
            load64(L2, Vj + (size_t)192 * LDQ);  CP_COMMIT();  // V4
            pv_compute(L0, 2);
            CP_WAIT(0);
            __syncthreads();
            pv_compute(L2, 3);
        }
    }

    // ---- epilogue: scale, tf32-round, store O^T col-major (== O row-major) ----
    const float invc = 1.0f / ((float)(bi + 1) + 1e-6f);
#pragma unroll
    for (int i = 0; i < 2; i++)
#pragma unroll
        for (int j = 0; j < 2; j++) {
#pragma unroll
            for (int t = 0; t < acc_o[i][j].num_elements; t++)
                acc_o[i][j].x[t] = to_tf32(acc_o[i][j].x[t] * invc);
            wmma::store_matrix_sync(
                g_o + ((size_t)(b * Sv + qbase + wn * 32 + j * 16)) * Hv
                    + h * HDv + wm * 32 + i * 16,
                acc_o[i][j], Hv, wmma::mem_col_major);
        }
}

// ===========================================================================
// launch
// ===========================================================================
extern "C" void kernel_launch(void* const* d_in, const int* in_sizes, int n_in,
                              void* d_out, int out_size)
{
    const float* X  = (const float*)d_in[0];
    const float* Wq = (const float*)d_in[1];
    const float* Wk = (const float*)d_in[2];
    const float* Wv = (const float*)d_in[3];
    const float* Wo = (const float*)d_in[4];
    float* out = (float*)d_out;

    float *qkv, *o, *xr, *wqkv, *wo;
    cudaGetSymbolAddress((void**)&qkv,  g_qkv);
    cudaGetSymbolAddress((void**)&o,    g_o);
    cudaGetSymbolAddress((void**)&xr,   g_xr);
    cudaGetSymbolAddress((void**)&wqkv, g_wqkv);
    cudaGetSymbolAddress((void**)&wo,   g_wo);

    cudaFuncSetAttribute(gemm_pipe, cudaFuncAttributeMaxDynamicSharedMemorySize, GEMM_SMEM);
    cudaFuncSetAttribute(attn_kernel, cudaFuncAttributeMaxDynamicSharedMemorySize, ATTN_SMEM);

    // single-launch tf32 rounding of X + Wq|Wk|Wv (into g_wqkv) + Wo
    round_all_k<<<(NX4 + 4 * NW4) / 256, 256>>>(
        (const float4*)X, (const float4*)Wq, (const float4*)Wk,
        (const float4*)Wv, (const float4*)Wo);

    // Fused QKV projection: [4096, 6144] = X @ [Wq;Wk;Wv]^T
    dim3 gq(LDQ / BN, Mtot / BM);    // (48, 16) = 768 CTAs
    gemm_pipe<<<gq, 256, GEMM_SMEM>>>(xr, wqkv, qkv, Mtot, LDQ, Hv, 1);

    dim3 ag(Sv / QT, NHv, Bv);       // (32, 16, 2)
    attn_kernel<<<ag, 256, ATTN_SMEM>>>();

    dim3 gg(Hv / BN, Mtot / BM);     // (16, 16)
    gemm_pipe<<<gg, 256, GEMM_SMEM>>>(o, wo, out, Mtot, Hv, Hv, 0);
}